// round 2
// baseline (speedup 1.0000x reference)
#include <cuda_runtime.h>

#define NF 27
#define FD 128
#define NPAIRS 351            // 27*26/2
#define OUT_STRIDE (NF*FD + NPAIRS)   // 3807
#define CHUNK 32
#define PAD 36                // transposed smem row pad (floats); keeps LDS.128 aligned,
                              // makes compute-phase bank-quads (9k+g)%8 distinct per g

// Warp-per-batch feature interaction.
//  - fill: coalesced LDG.32 of one k-chunk per feature row; same value feeds the
//    coalesced copy-out STG and the transposed smem scatter STS.
//  - compute: 28 lanes own 4x4 tiles over padded 28x28 feature grid; per k:
//    2x LDS.128 (conflict-free / broadcast) + 16 FFMA into registers.
//  - epilogue: predicated scatter of the 351 valid upper-tri dots.
__global__ void __launch_bounds__(128, 8)
fi_kernel(const float* __restrict__ in, float* __restrict__ out)
{
    __shared__ float sm[4][CHUNK][PAD];

    const int w    = threadIdx.x >> 5;
    const int lane = threadIdx.x & 31;
    const long b   = (long)blockIdx.x * 4 + w;

    const float* __restrict__ eb = in  + b * (long)(NF * FD);
    float*       __restrict__ ob = out + b * (long)OUT_STRIDE;

    // lane -> (gi, gj) tile mapping: 28 tiles = upper blocks (incl diag) of 7x7 groups
    int gi = 0, rem = lane;
    while (gi < 6 && rem >= 7 - gi) { rem -= 7 - gi; gi++; }
    const int gj = gi + rem;              // valid for lane < 28
    const bool active = (lane < 28);

    float acc[16];
#pragma unroll
    for (int t = 0; t < 16; t++) acc[t] = 0.0f;

    for (int kc = 0; kc < FD; kc += CHUNK) {
        // ---- fill chunk: copy-out + transposed smem stage ----
#pragma unroll
        for (int f = 0; f < NF; f++) {
            float v = eb[f * FD + kc + lane];     // coalesced 128B
            ob[f * FD + kc + lane] = v;           // coalesced copy-out
            sm[w][lane][f] = v;                   // transposed scatter (4-way, cheap)
        }
        __syncwarp();

        // ---- compute chunk ----
        if (active) {
            const float* base = &sm[w][0][0];
            const int oi = 4 * gi, oj = 4 * gj;
#pragma unroll
            for (int kk = 0; kk < CHUNK; kk++) {
                float4 a = *reinterpret_cast<const float4*>(base + kk * PAD + oi);
                float4 c = *reinterpret_cast<const float4*>(base + kk * PAD + oj);
                acc[0]  += a.x * c.x;  acc[1]  += a.x * c.y;
                acc[2]  += a.x * c.z;  acc[3]  += a.x * c.w;
                acc[4]  += a.y * c.x;  acc[5]  += a.y * c.y;
                acc[6]  += a.y * c.z;  acc[7]  += a.y * c.w;
                acc[8]  += a.z * c.x;  acc[9]  += a.z * c.y;
                acc[10] += a.z * c.z;  acc[11] += a.z * c.w;
                acc[12] += a.w * c.x;  acc[13] += a.w * c.y;
                acc[14] += a.w * c.z;  acc[15] += a.w * c.w;
            }
        }
        __syncwarp();   // protect smem reuse by next chunk's fill
    }

    // ---- epilogue: scatter valid upper-tri pairs ----
    if (active) {
        float* oint = ob + NF * FD;   // +3456
#pragma unroll
        for (int m = 0; m < 4; m++) {
#pragma unroll
            for (int n = 0; n < 4; n++) {
                int i = 4 * gi + m;
                int j = 4 * gj + n;
                if (j > i && j < NF && i < NF) {
                    int idx = (i * (53 - i)) / 2 + (j - i - 1);
                    oint[idx] = acc[m * 4 + n];
                }
            }
        }
    }
}

extern "C" void kernel_launch(void* const* d_in, const int* in_sizes, int n_in,
                              void* d_out, int out_size)
{
    const float* in = (const float*)d_in[0];
    float* out = (float*)d_out;
    const int B = in_sizes[0] / (NF * FD);   // 16384
    fi_kernel<<<B / 4, 128>>>(in, out);
}

// round 4
// speedup vs baseline: 1.0198x; 1.0198x over previous
#include <cuda_runtime.h>

#define NF 27
#define FD 128
#define NPAIRS 351                    // 27*26/2
#define OUT_STRIDE (NF*FD + NPAIRS)   // 3807
#define CHUNK 32
#define PAD 36                        // transposed smem row pad (floats)

// Warp-per-batch feature interaction, L1-wavefront optimized.
//  fill:    coalesced LDG.32 per feature row; copy-out STG.32; transposed
//           stage via STS.128 (4 features packed) — conflict-free.
//  compute: 28 lanes own 4x4 tiles of padded 28x28 grid; per k: 2x LDS.128
//           (7 distinct quad addresses -> broadcast) + 16 FFMA.
//  epilogue: stage 351 triu dots in smem, coalesced copy-out.
__global__ void __launch_bounds__(128, 8)
fi_kernel(const float* __restrict__ in, float* __restrict__ out)
{
    __shared__ float sm[4][CHUNK][PAD];

    const int w    = threadIdx.x >> 5;
    const int lane = threadIdx.x & 31;
    const long b   = (long)blockIdx.x * 4 + w;

    const float* __restrict__ eb = in  + b * (long)(NF * FD);
    float*       __restrict__ ob = out + b * (long)OUT_STRIDE;

    // lane -> (gi, gj): 28 upper (incl diag) blocks of the 7x7 group grid
    int gi = 0, rem = lane;
    while (gi < 6 && rem >= 7 - gi) { rem -= 7 - gi; gi++; }
    const int gj = gi + rem;
    const bool active = (lane < 28);

    float acc[16];
#pragma unroll
    for (int t = 0; t < 16; t++) acc[t] = 0.0f;

    for (int kc = 0; kc < FD; kc += CHUNK) {
        // ---- fill: load 4 feature rows, copy out, one STS.128 ----
#pragma unroll
        for (int f4 = 0; f4 < 7; f4++) {
            const int f0 = f4 * 4;
            float4 p;
            p.x = eb[(f0 + 0) * FD + kc + lane];
            p.y = eb[(f0 + 1) * FD + kc + lane];
            p.z = eb[(f0 + 2) * FD + kc + lane];
            p.w = (f0 + 3 < NF) ? eb[(f0 + 3) * FD + kc + lane] : 0.0f;

            ob[(f0 + 0) * FD + kc + lane] = p.x;
            ob[(f0 + 1) * FD + kc + lane] = p.y;
            ob[(f0 + 2) * FD + kc + lane] = p.z;
            if (f0 + 3 < NF) ob[(f0 + 3) * FD + kc + lane] = p.w;

            // transposed stage: features f0..f0+3 at k-row `lane`
            *reinterpret_cast<float4*>(&sm[w][lane][f0]) = p;   // conflict-free
        }
        __syncwarp();

        // ---- compute ----
        if (active) {
            const float* base = &sm[w][0][0];
            const int oi = 4 * gi, oj = 4 * gj;
#pragma unroll
            for (int kk = 0; kk < CHUNK; kk++) {
                float4 a = *reinterpret_cast<const float4*>(base + kk * PAD + oi);
                float4 c = *reinterpret_cast<const float4*>(base + kk * PAD + oj);
                acc[0]  += a.x * c.x;  acc[1]  += a.x * c.y;
                acc[2]  += a.x * c.z;  acc[3]  += a.x * c.w;
                acc[4]  += a.y * c.x;  acc[5]  += a.y * c.y;
                acc[6]  += a.y * c.z;  acc[7]  += a.y * c.w;
                acc[8]  += a.z * c.x;  acc[9]  += a.z * c.y;
                acc[10] += a.z * c.z;  acc[11] += a.z * c.w;
                acc[12] += a.w * c.x;  acc[13] += a.w * c.y;
                acc[14] += a.w * c.z;  acc[15] += a.w * c.w;
            }
        }
        __syncwarp();   // smem reused by next fill
    }

    // ---- epilogue: stage triu dots in smem, coalesced copy-out ----
    float* stage = &sm[w][0][0];   // 1152 floats available, need 351
    if (active) {
#pragma unroll
        for (int m = 0; m < 4; m++) {
#pragma unroll
            for (int n = 0; n < 4; n++) {
                int i = 4 * gi + m;
                int j = 4 * gj + n;
                if (j > i && j < NF && i < NF) {
                    int idx = (i * (53 - i)) / 2 + (j - i - 1);
                    stage[idx] = acc[m * 4 + n];
                }
            }
        }
    }
    __syncwarp();

    float* oint = ob + NF * FD;
#pragma unroll
    for (int t = 0; t < 11; t++) {
        int idx = t * 32 + lane;
        if (idx < NPAIRS) oint[idx] = stage[idx];
    }
}

extern "C" void kernel_launch(void* const* d_in, const int* in_sizes, int n_in,
                              void* d_out, int out_size)
{
    const float* in = (const float*)d_in[0];
    float* out = (float*)d_out;
    const int B = in_sizes[0] / (NF * FD);   // 16384
    fi_kernel<<<B / 4, 128>>>(in, out);
}